// round 6
// baseline (speedup 1.0000x reference)
#include <cuda_runtime.h>
#include <cuda_bf16.h>
#include <cstdint>

// Problem constants
#define NXg 512
#define NYg 512
#define NSENS 128
#define NT 2048
#define NPIX (NXg * NYg)

// Two half-channel scratch arrays: [s][t][4ch] as one float4 per (s,t).
// 4 MB each; a 128B line holds 8 consecutive t entries -> low line overfetch.
__device__ float4 g_scratchA[NSENS * NT];   // channels 0..3
__device__ float4 g_scratchB[NSENS * NT];   // channels 4..7

// ---------------------------------------------------------------------------
// Prep kernel: transpose sensor_data [B=4][C=2][S=128][T=2048] -> 2x [S][T][4]
// ---------------------------------------------------------------------------
__global__ __launch_bounds__(256) void das_transpose_kernel(
    const float* __restrict__ sd)
{
    int idx = blockIdx.x * blockDim.x + threadIdx.x;   // 0 .. 128*2048-1
    if (idx >= NSENS * NT) return;
    int s = idx >> 11;
    int t = idx & (NT - 1);

    const int bcStride = NSENS * NT;
    const float* base = sd + s * NT + t;

    float4 v0, v1;
    v0.x = base[0 * bcStride];
    v0.y = base[1 * bcStride];
    v0.z = base[2 * bcStride];
    v0.w = base[3 * bcStride];
    v1.x = base[4 * bcStride];
    v1.y = base[5 * bcStride];
    v1.z = base[6 * bcStride];
    v1.w = base[7 * bcStride];

    g_scratchA[idx] = v0;
    g_scratchB[idx] = v1;
}

// ---------------------------------------------------------------------------
// Main DAS kernel: one thread per pixel, 128-sensor loop.
// Warp covers a compact 8(iy) x 4(ix) patch; channel accumulation uses
// packed add.rn.f32x2 (two independent IEEE RN f32 adds -> bit-exact).
// ---------------------------------------------------------------------------
__global__ __launch_bounds__(256) void das_main_kernel(
    const int* __restrict__ sensor_xy,   // [128][2] int32
    float* __restrict__ out)             // [8][NPIX]
{
    __shared__ float2 sxy[NSENS];

    const int tid  = threadIdx.x;        // 0..255
    const int lane = tid & 31;
    const int w    = tid >> 5;           // 0..7

    if (tid < NSENS) {
        int2 xy = ((const int2*)sensor_xy)[tid];
        sxy[tid] = make_float2((float)xy.x, (float)xy.y);
    }
    __syncthreads();

    // Warp patch: 8 iy x 4 ix. Warps tile 2x4 over the 16x16 block tile.
    const int ly = lane & 7;
    const int lx = lane >> 3;
    const int wy = w & 1;
    const int wx = w >> 1;

    const int iy = blockIdx.x * 16 + wy * 8 + ly;
    const int ix = blockIdx.y * 16 + wx * 4 + lx;

    const float fix = (float)ix;
    const float fiy = (float)iy;

    // XLA chain (bit-exact, validated R3): dis * fl(fl(1/VS)*fl(1/DT)).
    const float K = (1.0f / 1550.0f) * (1.0f / 2.5e-8f);

    // Packed accumulators: each b64 holds two f32 lanes, init 0.0f|0.0f.
    unsigned long long a0 = 0ull, a1 = 0ull, a2 = 0ull, a3 = 0ull;

    const ulonglong2* __restrict__ pa = (const ulonglong2*)g_scratchA;
    const ulonglong2* __restrict__ pb = (const ulonglong2*)g_scratchB;

    #pragma unroll 8
    for (int s = 0; s < NSENS; ++s) {
        float2 c = sxy[s];
        float dx = __fmul_rn(c.x - fix, 1e-4f);
        float dy = __fmul_rn(c.y - fiy, 1e-4f);
        float r2 = __fadd_rn(__fmul_rn(dx, dx), __fmul_rn(dy, dy));
        float dis = __fsqrt_rn(r2);
        int t = (int)__fmul_rn(dis, K);

        unsigned off = ((unsigned)s << 11) + (unsigned)t;
        ulonglong2 v0 = __ldg(pa + off);
        ulonglong2 v1 = __ldg(pb + off);

        asm("add.rn.f32x2 %0, %0, %1;" : "+l"(a0) : "l"(v0.x));
        asm("add.rn.f32x2 %0, %0, %1;" : "+l"(a1) : "l"(v0.y));
        asm("add.rn.f32x2 %0, %0, %1;" : "+l"(a2) : "l"(v1.x));
        asm("add.rn.f32x2 %0, %0, %1;" : "+l"(a3) : "l"(v1.y));
    }

    const int p = ix * NYg + iy;
    unsigned lo, hi;
    asm("mov.b64 {%0,%1}, %2;" : "=r"(lo), "=r"(hi) : "l"(a0));
    out[0 * NPIX + p] = __uint_as_float(lo);
    out[1 * NPIX + p] = __uint_as_float(hi);
    asm("mov.b64 {%0,%1}, %2;" : "=r"(lo), "=r"(hi) : "l"(a1));
    out[2 * NPIX + p] = __uint_as_float(lo);
    out[3 * NPIX + p] = __uint_as_float(hi);
    asm("mov.b64 {%0,%1}, %2;" : "=r"(lo), "=r"(hi) : "l"(a2));
    out[4 * NPIX + p] = __uint_as_float(lo);
    out[5 * NPIX + p] = __uint_as_float(hi);
    asm("mov.b64 {%0,%1}, %2;" : "=r"(lo), "=r"(hi) : "l"(a3));
    out[6 * NPIX + p] = __uint_as_float(lo);
    out[7 * NPIX + p] = __uint_as_float(hi);
}

// ---------------------------------------------------------------------------
// Entry point
// ---------------------------------------------------------------------------
extern "C" void kernel_launch(void* const* d_in, const int* in_sizes, int n_in,
                              void* d_out, int out_size)
{
    const float* sensor_data = (const float*)d_in[0];   // (4,2,128,2048) f32
    const int*   sensor_xy   = (const int*)d_in[1];     // (128,2) i32
    float*       out         = (float*)d_out;           // (4,2,512,512) f32

    das_transpose_kernel<<<(NSENS * NT + 255) / 256, 256>>>(sensor_data);

    dim3 block(256);
    dim3 grid(NYg / 16, NXg / 16);
    das_main_kernel<<<grid, block>>>(sensor_xy, out);
}